// round 1
// baseline (speedup 1.0000x reference)
#include <cuda_runtime.h>
#include <math.h>

// Problem constants (fixed by the reference)
#define NN  50000
#define EE  800000
#define GG  128
#define FIN_EMB 64
#define HH  108          // hidden = out = 108
#define CH4 (HH/4)       // 27 float4 chunks per row

#define RPB 32           // rows per block in plain GEMM
#define NAR 16           // rows per block in node-apply

// ---------------- scratch (no allocations allowed) ----------------
__device__ __align__(16) float g_h0 [NN*HH];
__device__ __align__(16) float g_m  [NN*HH];
__device__ __align__(16) float g_agg[NN*HH];
__device__ __align__(16) float g_h1 [NN*HH];
__device__ __align__(16) float g_s  [GG*HH];
__device__ float g_deg[NN];
__device__ float g_cnt[GG];

// ---------------- vector reduction (fire-and-forget atomic add) ----------------
__device__ __forceinline__ void red_add_v4(float* a, float4 v) {
    asm volatile("red.global.add.v4.f32 [%0], {%1, %2, %3, %4};"
                 :: "l"(a), "f"(v.x), "f"(v.y), "f"(v.z), "f"(v.w)
                 : "memory");
}

// ---------------- Y[n,108] = act(X[n,fin] @ W[fin,108] + b) ----------------
// W staged in shared; each thread (j = out column) accumulates RPB rows so a
// shared W read is amortized over RPB FMAs -> FMA-bound.
template<bool RELU>
__global__ void gemm_bias(const float* __restrict__ X, const float* __restrict__ W,
                          const float* __restrict__ b, float* __restrict__ Y,
                          int n, int fin) {
    extern __shared__ float sh[];
    float* Ws = sh;                 // fin*HH
    float* bs = Ws + fin * HH;      // HH
    float* xs = bs + HH;            // RPB*fin
    const int tid = threadIdx.x;    // 128 threads

    for (int i = tid; i < fin * HH; i += blockDim.x) Ws[i] = W[i];
    if (tid < HH) bs[tid] = b[tid];

    const int row0 = blockIdx.x * RPB;
    for (int i = tid; i < RPB * fin; i += blockDim.x) {
        int r = i / fin, k = i - r * fin;
        int row = row0 + r;
        xs[i] = (row < n) ? X[(size_t)row * fin + k] : 0.f;
    }
    __syncthreads();

    if (tid < HH) {
        float acc[RPB];
        #pragma unroll
        for (int r = 0; r < RPB; r++) acc[r] = bs[tid];
        for (int k = 0; k < fin; k += 4) {
            float w0 = Ws[(k+0)*HH + tid];
            float w1 = Ws[(k+1)*HH + tid];
            float w2 = Ws[(k+2)*HH + tid];
            float w3 = Ws[(k+3)*HH + tid];
            #pragma unroll
            for (int r = 0; r < RPB; r++) {
                float4 x4 = *reinterpret_cast<const float4*>(&xs[r*fin + k]);
                acc[r] = fmaf(x4.x, w0, acc[r]);
                acc[r] = fmaf(x4.y, w1, acc[r]);
                acc[r] = fmaf(x4.z, w2, acc[r]);
                acc[r] = fmaf(x4.w, w3, acc[r]);
            }
        }
        #pragma unroll
        for (int r = 0; r < RPB; r++) {
            int row = row0 + r;
            if (row < n) {
                float v = acc[r];
                if (RELU) v = fmaxf(v, 0.f);
                Y[(size_t)row * HH + tid] = v;
            }
        }
    }
}

// ---------------- degree (over dst) + per-graph node count ----------------
__global__ void deg_cnt_kernel(const int* __restrict__ dst, const int* __restrict__ gid,
                               float* __restrict__ deg, float* __restrict__ cnt) {
    int t = blockIdx.x * blockDim.x + threadIdx.x;
    if (t < EE) atomicAdd(&deg[dst[t]], 1.f);
    if (t < NN) atomicAdd(&cnt[gid[t]], 1.f);
}

// ---------------- agg[dst] += m[src] over all edges (v4 atomics) ----------------
__global__ void scatter_add(const float* __restrict__ m, const int* __restrict__ src,
                            const int* __restrict__ dst, float* __restrict__ agg) {
    int t = blockIdx.x * blockDim.x + threadIdx.x;
    if (t >= EE * CH4) return;
    int e = t / CH4;
    int c = t - e * CH4;
    int s = src[e], d = dst[e];
    float4 v = *reinterpret_cast<const float4*>(m + (size_t)s * HH + c * 4);
    red_add_v4(agg + (size_t)d * HH + c * 4, v);
}

// ---------------- fused node apply ----------------
// c = agg/max(deg,1); bundle = [h,c] @ Wn + bn; L2-normalize row; out = h + relu(.)
__global__ void node_apply(const float* __restrict__ Hin, const float* __restrict__ agg,
                           const float* __restrict__ deg, const float* __restrict__ W,
                           const float* __restrict__ b, float* __restrict__ Hout) {
    const int FIN = 2 * HH;  // 216
    extern __shared__ float sh[];
    float* Ws  = sh;                    // 216*108
    float* bs  = Ws + FIN * HH;         // 108
    float* xs  = bs + HH;               // NAR*216
    float* red = xs + NAR * FIN;        // 4*NAR warp partials + NAR norms

    const int tid  = threadIdx.x;       // 128
    const int warp = tid >> 5, lane = tid & 31;

    for (int i = tid; i < FIN * HH; i += blockDim.x) Ws[i] = W[i];
    if (tid < HH) bs[tid] = b[tid];

    const int row0 = blockIdx.x * NAR;
    for (int i = tid; i < NAR * HH; i += blockDim.x) {
        int r = i / HH, k = i - r * HH;
        int row = row0 + r;
        if (row < NN) {
            xs[r*FIN + k]      = Hin[(size_t)row * HH + k];
            float dg           = fmaxf(deg[row], 1.f);
            xs[r*FIN + HH + k] = agg[(size_t)row * HH + k] / dg;
        } else {
            xs[r*FIN + k] = 0.f;
            xs[r*FIN + HH + k] = 0.f;
        }
    }
    __syncthreads();

    float acc[NAR];
    if (tid < HH) {
        #pragma unroll
        for (int r = 0; r < NAR; r++) acc[r] = bs[tid];
        for (int k = 0; k < FIN; k += 4) {
            float w0 = Ws[(k+0)*HH + tid];
            float w1 = Ws[(k+1)*HH + tid];
            float w2 = Ws[(k+2)*HH + tid];
            float w3 = Ws[(k+3)*HH + tid];
            #pragma unroll
            for (int r = 0; r < NAR; r++) {
                float4 x4 = *reinterpret_cast<const float4*>(&xs[r*FIN + k]);
                acc[r] = fmaf(x4.x, w0, acc[r]);
                acc[r] = fmaf(x4.y, w1, acc[r]);
                acc[r] = fmaf(x4.z, w2, acc[r]);
                acc[r] = fmaf(x4.w, w3, acc[r]);
            }
        }
    }

    // block-wide sum of acc^2 per row (L2 norm)
    float v[NAR];
    #pragma unroll
    for (int r = 0; r < NAR; r++) v[r] = (tid < HH) ? acc[r] * acc[r] : 0.f;
    #pragma unroll
    for (int off = 16; off > 0; off >>= 1) {
        #pragma unroll
        for (int r = 0; r < NAR; r++)
            v[r] += __shfl_down_sync(0xffffffffu, v[r], off);
    }
    if (lane == 0) {
        #pragma unroll
        for (int r = 0; r < NAR; r++) red[warp * NAR + r] = v[r];
    }
    __syncthreads();
    if (tid < NAR) {
        float s = red[tid] + red[NAR + tid] + red[2*NAR + tid] + red[3*NAR + tid];
        red[4*NAR + tid] = sqrtf(s);
    }
    __syncthreads();

    if (tid < HH) {
        #pragma unroll
        for (int r = 0; r < NAR; r++) {
            int row = row0 + r;
            if (row < NN) {
                float nrm = fmaxf(red[4*NAR + r], 1e-12f);
                float hin = xs[r*FIN + tid];
                Hout[(size_t)row * HH + tid] = hin + fmaxf(acc[r] / nrm, 0.f);
            }
        }
    }
}

// ---------------- per-graph sum via v4 atomics ----------------
__global__ void graph_pool(const float* __restrict__ Hfin, const int* __restrict__ gid,
                           float* __restrict__ s) {
    int t = blockIdx.x * blockDim.x + threadIdx.x;
    if (t >= NN * CH4) return;
    int nidx = t / CH4;
    int c    = t - nidx * CH4;
    int g    = gid[nidx];
    float4 v = *reinterpret_cast<const float4*>(Hfin + (size_t)nidx * HH + c * 4);
    red_add_v4(s + (size_t)g * HH + c * 4, v);
}

__global__ void finalize(const float* __restrict__ s, const float* __restrict__ cnt,
                         float* __restrict__ out) {
    int t = blockIdx.x * blockDim.x + threadIdx.x;
    if (t < GG * HH) {
        int g = t / HH;
        out[t] = s[t] / fmaxf(cnt[g], 1.f);
    }
}

// ---------------- launch ----------------
extern "C" void kernel_launch(void* const* d_in, const int* in_sizes, int n_in,
                              void* d_out, int out_size) {
    const float* nodes_feat = (const float*)d_in[0];
    // d_in[1..3] (edges_feat, norms) unused by the reference math
    const int*   src  = (const int*)d_in[4];
    const int*   dst  = (const int*)d_in[5];
    const int*   gid  = (const int*)d_in[6];
    const float* W_emb = (const float*)d_in[7];
    const float* b_emb = (const float*)d_in[8];
    const float* Wp1   = (const float*)d_in[9];
    const float* bp1   = (const float*)d_in[10];
    const float* Wn1   = (const float*)d_in[11];
    const float* bn1   = (const float*)d_in[12];
    const float* Wp2   = (const float*)d_in[13];
    const float* bp2   = (const float*)d_in[14];
    const float* Wn2   = (const float*)d_in[15];
    const float* bn2   = (const float*)d_in[16];
    float* out = (float*)d_out;

    float *p_h0, *p_m, *p_agg, *p_h1, *p_s, *p_deg, *p_cnt;
    cudaGetSymbolAddress((void**)&p_h0,  g_h0);
    cudaGetSymbolAddress((void**)&p_m,   g_m);
    cudaGetSymbolAddress((void**)&p_agg, g_agg);
    cudaGetSymbolAddress((void**)&p_h1,  g_h1);
    cudaGetSymbolAddress((void**)&p_s,   g_s);
    cudaGetSymbolAddress((void**)&p_deg, g_deg);
    cudaGetSymbolAddress((void**)&p_cnt, g_cnt);

    const int smem_emb = (FIN_EMB*HH + HH + RPB*FIN_EMB) * 4;        // ~36 KB
    const int smem_p   = (HH*HH + HH + RPB*HH) * 4;                  // ~61 KB
    const int smem_na  = (2*HH*HH + HH + NAR*2*HH + 5*NAR) * 4;      // ~108 KB
    cudaFuncSetAttribute(gemm_bias<false>, cudaFuncAttributeMaxDynamicSharedMemorySize, smem_p);
    cudaFuncSetAttribute(gemm_bias<true>,  cudaFuncAttributeMaxDynamicSharedMemorySize, smem_p);
    cudaFuncSetAttribute(node_apply,       cudaFuncAttributeMaxDynamicSharedMemorySize, smem_na);

    cudaMemsetAsync(p_agg, 0, (size_t)NN*HH*sizeof(float));
    cudaMemsetAsync(p_deg, 0, (size_t)NN*sizeof(float));
    cudaMemsetAsync(p_s,   0, (size_t)GG*HH*sizeof(float));
    cudaMemsetAsync(p_cnt, 0, (size_t)GG*sizeof(float));

    const int gemm_blocks = (NN + RPB - 1) / RPB;
    const int na_blocks   = (NN + NAR - 1) / NAR;
    const int scat_blocks = (EE * CH4 + 255) / 256;

    // h0 = X @ W_emb + b_emb
    gemm_bias<false><<<gemm_blocks, 128, smem_emb>>>(nodes_feat, W_emb, b_emb, p_h0, NN, FIN_EMB);
    // degrees + graph counts (reused everywhere)
    deg_cnt_kernel<<<(EE + 255) / 256, 256>>>(dst, gid, p_deg, p_cnt);

    // ---- layer 1 ----
    gemm_bias<true><<<gemm_blocks, 128, smem_p>>>(p_h0, Wp1, bp1, p_m, NN, HH);
    scatter_add<<<scat_blocks, 256>>>(p_m, src, dst, p_agg);
    node_apply<<<na_blocks, 128, smem_na>>>(p_h0, p_agg, p_deg, Wn1, bn1, p_h1);

    // ---- layer 2 ----
    cudaMemsetAsync(p_agg, 0, (size_t)NN*HH*sizeof(float));
    gemm_bias<true><<<gemm_blocks, 128, smem_p>>>(p_h1, Wp2, bp2, p_m, NN, HH);
    scatter_add<<<scat_blocks, 256>>>(p_m, src, dst, p_agg);
    node_apply<<<na_blocks, 128, smem_na>>>(p_h1, p_agg, p_deg, Wn2, bn2, p_h0);

    // ---- readout ----
    graph_pool<<<(NN * CH4 + 255) / 256, 256>>>(p_h0, gid, p_s);
    finalize<<<(GG * HH + 127) / 128, 128>>>(p_s, p_cnt, out);
}

// round 2
// speedup vs baseline: 1.8136x; 1.8136x over previous
#include <cuda_runtime.h>
#include <math.h>

// Problem constants (fixed by the reference)
#define NN  50000
#define EE  800000
#define GG  128
#define FIN_EMB 64
#define HH  108          // hidden = out = 108
#define CH4 (HH/4)       // 27 float4 chunks per row

#define RPB 16           // rows per group in GEMM (4 groups/block -> 64 rows/block)
#define NAR 16           // rows per group in node-apply

// ---------------- scratch (no allocations allowed) ----------------
__device__ __align__(16) float g_h0 [NN*HH];
__device__ __align__(16) float g_m  [NN*HH];
__device__ __align__(16) float g_agg[NN*HH];
__device__ __align__(16) float g_h1 [NN*HH];
__device__ __align__(16) float g_s  [GG*HH];
__device__ int   g_degi[NN];
__device__ int   g_off [NN];
__device__ int   g_cur [NN];
__device__ int   g_csr [EE];
__device__ int   g_bsum[128];
__device__ float g_cnt[GG];

// ================= dense: Y[n,108] = act(X[n,FIN] @ W + b) =================
// 512 threads = 4 groups x 128 lanes. Output padded to 128 columns (zero W).
// W staged once per block, serves 4*RPB rows.
template<bool RELU, int FIN>
__global__ __launch_bounds__(512) void gemm_v2(
        const float* __restrict__ X, const float* __restrict__ W,
        const float* __restrict__ b, float* __restrict__ Y, int n) {
    extern __shared__ float sh[];
    float* Ws = sh;                  // FIN*128
    float* bs = Ws + FIN * 128;      // 128
    float* xs = bs + 128;            // 4*RPB*FIN
    const int tid = threadIdx.x;
    const int t = tid & 127, g = tid >> 7;

    for (int i = tid; i < FIN * 128; i += 512) {
        int k = i >> 7, c = i & 127;
        Ws[i] = (c < HH) ? W[k * HH + c] : 0.f;
    }
    if (tid < 128) bs[tid] = (tid < HH) ? b[tid] : 0.f;

    const int row0 = blockIdx.x * (4 * RPB) + g * RPB;
    float* xsg = xs + g * (RPB * FIN);
    const float4* Xb = (const float4*)(X + (size_t)row0 * FIN);
    const int NV = RPB * FIN / 4;
    for (int i = t; i < NV; i += 128) {
        int r = i / (FIN / 4);
        float4 v = (row0 + r < n) ? Xb[i] : make_float4(0.f, 0.f, 0.f, 0.f);
        ((float4*)xsg)[i] = v;
    }
    __syncthreads();

    float acc[RPB];
    #pragma unroll
    for (int r = 0; r < RPB; r++) acc[r] = bs[t];
    for (int k = 0; k < FIN; k += 4) {
        float w0 = Ws[(k+0)*128 + t];
        float w1 = Ws[(k+1)*128 + t];
        float w2 = Ws[(k+2)*128 + t];
        float w3 = Ws[(k+3)*128 + t];
        #pragma unroll
        for (int r = 0; r < RPB; r++) {
            float4 x4 = *(const float4*)&xsg[r*FIN + k];
            acc[r] = fmaf(x4.x, w0, acc[r]);
            acc[r] = fmaf(x4.y, w1, acc[r]);
            acc[r] = fmaf(x4.z, w2, acc[r]);
            acc[r] = fmaf(x4.w, w3, acc[r]);
        }
    }

    if (t < HH) {
        #pragma unroll
        for (int r = 0; r < RPB; r++) {
            int row = row0 + r;
            if (row < n) {
                float v = acc[r];
                if (RELU) v = fmaxf(v, 0.f);
                Y[(size_t)row * HH + t] = v;
            }
        }
    }
}

// ================= fused node apply =================
// c = agg/max(deg,1); bundle = [h,c]@Wn + bn; L2-normalize; out = h + relu(.)
// 512 threads = 4 groups x 128 lanes, padded columns, 64 rows/block.
__global__ __launch_bounds__(512) void node_apply_v2(
        const float* __restrict__ Hin, const float* __restrict__ agg,
        const int* __restrict__ degi, const float* __restrict__ W,
        const float* __restrict__ b, float* __restrict__ Hout) {
    const int FIN = 216;
    extern __shared__ float sh[];
    float* Ws  = sh;                    // 216*128
    float* bs  = Ws + FIN * 128;        // 128
    float* xs  = bs + 128;              // 4*NAR*216
    float* red = xs + 4 * NAR * FIN;    // 4 * (4*NAR + NAR)

    const int tid = threadIdx.x;
    const int t = tid & 127, g = tid >> 7;
    const int warp = t >> 5, lane = t & 31;

    for (int i = tid; i < FIN * 128; i += 512) {
        int k = i >> 7, c = i & 127;
        Ws[i] = (c < HH) ? W[k * HH + c] : 0.f;
    }
    if (tid < 128) bs[tid] = (tid < HH) ? b[tid] : 0.f;

    const int row0 = blockIdx.x * (4 * NAR) + g * NAR;
    float* xsg = xs + g * (NAR * FIN);
    const float4* H4 = (const float4*)Hin;
    const float4* A4 = (const float4*)agg;
    for (int i = t; i < NAR * CH4; i += 128) {
        int r = i / CH4, c = i - r * CH4;
        int row = row0 + r;
        float4 h = make_float4(0.f,0.f,0.f,0.f), a = h;
        if (row < NN) {
            h = H4[(size_t)row * CH4 + c];
            a = A4[(size_t)row * CH4 + c];
            float inv = 1.f / fmaxf((float)degi[row], 1.f);
            a.x *= inv; a.y *= inv; a.z *= inv; a.w *= inv;
        }
        *(float4*)&xsg[r*FIN + c*4]       = h;
        *(float4*)&xsg[r*FIN + HH + c*4]  = a;
    }
    __syncthreads();

    float acc[NAR];
    #pragma unroll
    for (int r = 0; r < NAR; r++) acc[r] = bs[t];
    for (int k = 0; k < FIN; k += 4) {
        float w0 = Ws[(k+0)*128 + t];
        float w1 = Ws[(k+1)*128 + t];
        float w2 = Ws[(k+2)*128 + t];
        float w3 = Ws[(k+3)*128 + t];
        #pragma unroll
        for (int r = 0; r < NAR; r++) {
            float4 x4 = *(const float4*)&xsg[r*FIN + k];
            acc[r] = fmaf(x4.x, w0, acc[r]);
            acc[r] = fmaf(x4.y, w1, acc[r]);
            acc[r] = fmaf(x4.z, w2, acc[r]);
            acc[r] = fmaf(x4.w, w3, acc[r]);
        }
    }

    // row L2 norms: padded lanes contribute exact zeros
    float* redg = red + g * (5 * NAR);
    #pragma unroll
    for (int r = 0; r < NAR; r++) {
        float v = acc[r] * acc[r];
        #pragma unroll
        for (int off = 16; off > 0; off >>= 1)
            v += __shfl_down_sync(0xffffffffu, v, off);
        if (lane == 0) redg[warp * NAR + r] = v;
    }
    __syncthreads();
    if (t < NAR) {
        float s = redg[t] + redg[NAR+t] + redg[2*NAR+t] + redg[3*NAR+t];
        redg[4*NAR + t] = fmaxf(sqrtf(s), 1e-12f);
    }
    __syncthreads();

    if (t < HH) {
        #pragma unroll
        for (int r = 0; r < NAR; r++) {
            int row = row0 + r;
            if (row < NN) {
                float inv = 1.f / redg[4*NAR + r];
                Hout[(size_t)row * HH + t] = xsg[r*FIN + t] + fmaxf(acc[r] * inv, 0.f);
            }
        }
    }
}

// ================= CSR build =================
__global__ void deg_cnt_kernel(const int* __restrict__ dst, const int* __restrict__ gid,
                               int* __restrict__ degi, float* __restrict__ cnt) {
    int tk = blockIdx.x * blockDim.x + threadIdx.x;
    if (tk < EE) atomicAdd(&degi[dst[tk]], 1);
    if (tk < NN) atomicAdd(&cnt[gid[tk]], 1.f);
}

__global__ void scan1(const int* __restrict__ degi, int* __restrict__ off,
                      int* __restrict__ bsum) {   // 512 thr, 512 elems/block
    __shared__ int shi[512];
    int i = blockIdx.x * 512 + threadIdx.x;
    int x = (i < NN) ? degi[i] : 0;
    shi[threadIdx.x] = x;
    __syncthreads();
    for (int d = 1; d < 512; d <<= 1) {
        int v = (threadIdx.x >= d) ? shi[threadIdx.x - d] : 0;
        __syncthreads();
        shi[threadIdx.x] += v;
        __syncthreads();
    }
    if (i < NN) off[i] = shi[threadIdx.x] - x;       // exclusive within block
    if (threadIdx.x == 511) bsum[blockIdx.x] = shi[511];
}

__global__ void scan2(int* __restrict__ bsum, int nb) {  // 1 block, 128 thr
    __shared__ int shi[128];
    int x = (threadIdx.x < nb) ? bsum[threadIdx.x] : 0;
    shi[threadIdx.x] = x;
    __syncthreads();
    for (int d = 1; d < 128; d <<= 1) {
        int v = (threadIdx.x >= d) ? shi[threadIdx.x - d] : 0;
        __syncthreads();
        shi[threadIdx.x] += v;
        __syncthreads();
    }
    if (threadIdx.x < nb) bsum[threadIdx.x] = shi[threadIdx.x] - x;  // exclusive
}

__global__ void scan3(int* __restrict__ off, const int* __restrict__ bsum) {
    int i = blockIdx.x * blockDim.x + threadIdx.x;
    if (i < NN) off[i] += bsum[i >> 9];
}

__global__ void csr_fill(const int* __restrict__ src, const int* __restrict__ dst,
                         int* __restrict__ cur, int* __restrict__ csr) {
    int e = blockIdx.x * blockDim.x + threadIdx.x;
    if (e < EE) {
        int d = dst[e];
        int p = atomicAdd(&cur[d], 1);
        csr[p] = src[e];
    }
}

// ================= gather aggregation: one warp per node =================
__global__ void gather_agg(const float* __restrict__ m, const int* __restrict__ off,
                           const int* __restrict__ csr, float* __restrict__ agg) {
    int w = (blockIdx.x * blockDim.x + threadIdx.x) >> 5;
    int lane = threadIdx.x & 31;
    if (w >= NN) return;
    int s0 = off[w];
    int s1 = (w + 1 < NN) ? off[w + 1] : EE;
    float4 acc = make_float4(0.f, 0.f, 0.f, 0.f);
    const float4* m4 = (const float4*)m;
    for (int j = s0; j < s1; j++) {
        int s = csr[j];
        if (lane < CH4) {
            float4 v = m4[(size_t)s * CH4 + lane];
            acc.x += v.x; acc.y += v.y; acc.z += v.z; acc.w += v.w;
        }
    }
    if (lane < CH4) ((float4*)agg)[(size_t)w * CH4 + lane] = acc;
}

// ================= readout =================
__device__ __forceinline__ void red_add_v4(float* a, float4 v) {
    asm volatile("red.global.add.v4.f32 [%0], {%1, %2, %3, %4};"
                 :: "l"(a), "f"(v.x), "f"(v.y), "f"(v.z), "f"(v.w)
                 : "memory");
}

__global__ void graph_pool(const float* __restrict__ Hfin, const int* __restrict__ gid,
                           float* __restrict__ s) {
    int tk = blockIdx.x * blockDim.x + threadIdx.x;
    if (tk >= NN * CH4) return;
    int nidx = tk / CH4;
    int c    = tk - nidx * CH4;
    int g    = gid[nidx];
    float4 v = *reinterpret_cast<const float4*>(Hfin + (size_t)nidx * HH + c * 4);
    red_add_v4(s + (size_t)g * HH + c * 4, v);
}

__global__ void finalize(const float* __restrict__ s, const float* __restrict__ cnt,
                         float* __restrict__ out) {
    int tk = blockIdx.x * blockDim.x + threadIdx.x;
    if (tk < GG * HH) {
        int g = tk / HH;
        out[tk] = s[tk] / fmaxf(cnt[g], 1.f);
    }
}

// ================= launch =================
extern "C" void kernel_launch(void* const* d_in, const int* in_sizes, int n_in,
                              void* d_out, int out_size) {
    const float* nodes_feat = (const float*)d_in[0];
    const int*   src  = (const int*)d_in[4];
    const int*   dst  = (const int*)d_in[5];
    const int*   gid  = (const int*)d_in[6];
    const float* W_emb = (const float*)d_in[7];
    const float* b_emb = (const float*)d_in[8];
    const float* Wp1   = (const float*)d_in[9];
    const float* bp1   = (const float*)d_in[10];
    const float* Wn1   = (const float*)d_in[11];
    const float* bn1   = (const float*)d_in[12];
    const float* Wp2   = (const float*)d_in[13];
    const float* bp2   = (const float*)d_in[14];
    const float* Wn2   = (const float*)d_in[15];
    const float* bn2   = (const float*)d_in[16];
    float* out = (float*)d_out;

    float *p_h0, *p_m, *p_agg, *p_h1, *p_s, *p_cnt;
    int *p_degi, *p_off, *p_cur, *p_csr, *p_bsum;
    cudaGetSymbolAddress((void**)&p_h0,   g_h0);
    cudaGetSymbolAddress((void**)&p_m,    g_m);
    cudaGetSymbolAddress((void**)&p_agg,  g_agg);
    cudaGetSymbolAddress((void**)&p_h1,   g_h1);
    cudaGetSymbolAddress((void**)&p_s,    g_s);
    cudaGetSymbolAddress((void**)&p_cnt,  g_cnt);
    cudaGetSymbolAddress((void**)&p_degi, g_degi);
    cudaGetSymbolAddress((void**)&p_off,  g_off);
    cudaGetSymbolAddress((void**)&p_cur,  g_cur);
    cudaGetSymbolAddress((void**)&p_csr,  g_csr);
    cudaGetSymbolAddress((void**)&p_bsum, g_bsum);

    const int smem_emb  = (FIN_EMB*128 + 128 + 4*RPB*FIN_EMB) * 4;   // ~49.7 KB
    const int smem_pool = (HH*128 + 128 + 4*RPB*HH) * 4;             // ~83.5 KB
    const int smem_na   = (216*128 + 128 + 4*NAR*216 + 4*5*NAR) * 4; // ~167.7 KB
    cudaFuncSetAttribute(gemm_v2<false, FIN_EMB>, cudaFuncAttributeMaxDynamicSharedMemorySize, smem_emb);
    cudaFuncSetAttribute(gemm_v2<true,  HH>,      cudaFuncAttributeMaxDynamicSharedMemorySize, smem_pool);
    cudaFuncSetAttribute(node_apply_v2,           cudaFuncAttributeMaxDynamicSharedMemorySize, smem_na);

    cudaMemsetAsync(p_degi, 0, (size_t)NN * sizeof(int));
    cudaMemsetAsync(p_s,    0, (size_t)GG * HH * sizeof(float));
    cudaMemsetAsync(p_cnt,  0, (size_t)GG * sizeof(float));

    const int gemm_blocks = (NN + 4*RPB - 1) / (4*RPB);   // 782
    const int na_blocks   = (NN + 4*NAR - 1) / (4*NAR);   // 782
    const int nb_scan     = (NN + 511) / 512;             // 98
    const int gath_blocks = (NN * 32 + 255) / 256;        // 6250

    // h0 = X @ W_emb + b_emb
    gemm_v2<false, FIN_EMB><<<gemm_blocks, 512, smem_emb>>>(nodes_feat, W_emb, b_emb, p_h0, NN);

    // degrees + graph counts, then CSR by dst (shared by both layers)
    deg_cnt_kernel<<<(EE + 255) / 256, 256>>>(dst, gid, p_degi, p_cnt);
    scan1<<<nb_scan, 512>>>(p_degi, p_off, p_bsum);
    scan2<<<1, 128>>>(p_bsum, nb_scan);
    scan3<<<(NN + 255) / 256, 256>>>(p_off, p_bsum);
    cudaMemcpyAsync(p_cur, p_off, (size_t)NN * sizeof(int), cudaMemcpyDeviceToDevice);
    csr_fill<<<(EE + 255) / 256, 256>>>(src, dst, p_cur, p_csr);

    // ---- layer 1 ----
    gemm_v2<true, HH><<<gemm_blocks, 512, smem_pool>>>(p_h0, Wp1, bp1, p_m, NN);
    gather_agg<<<gath_blocks, 256>>>(p_m, p_off, p_csr, p_agg);
    node_apply_v2<<<na_blocks, 512, smem_na>>>(p_h0, p_agg, p_degi, Wn1, bn1, p_h1);

    // ---- layer 2 ----
    gemm_v2<true, HH><<<gemm_blocks, 512, smem_pool>>>(p_h1, Wp2, bp2, p_m, NN);
    gather_agg<<<gath_blocks, 256>>>(p_m, p_off, p_csr, p_agg);
    node_apply_v2<<<na_blocks, 512, smem_na>>>(p_h1, p_agg, p_degi, Wn2, bn2, p_h0);

    // ---- readout ----
    graph_pool<<<(NN * CH4 + 255) / 256, 256>>>(p_h0, gid, p_s);
    finalize<<<(GG * HH + 127) / 128, 128>>>(p_s, p_cnt, out);
}

// round 3
// speedup vs baseline: 1.9079x; 1.0520x over previous
#include <cuda_runtime.h>
#include <math.h>
#include <stdint.h>

// Problem constants (fixed by the reference)
#define NN  50000
#define EE  800000
#define GG  128
#define FIN_EMB 64
#define HH  108          // hidden = out = 108
#define CH4 (HH/4)       // 27 float4 chunks per row

#define RPB 16           // rows per group in GEMM (4 groups/block -> 64 rows/block)
#define NAR 16           // rows per group in node-apply

// ---------------- scratch (no allocations allowed) ----------------
__device__ __align__(16) float g_h0 [NN*HH];
__device__ __align__(16) float g_m  [NN*HH];
__device__ __align__(16) float g_agg[NN*HH];
__device__ __align__(16) float g_h1 [NN*HH];
__device__ __align__(16) float g_s  [GG*HH];
__device__ int   g_degi[NN];
__device__ int   g_off [NN];
__device__ int   g_cur [NN];
__device__ int   g_csr [EE];
__device__ int   g_bsum[128];
__device__ float g_cnt[GG];

// ---------------- packed f32x2 helpers (Blackwell sm_100+) ----------------
__device__ __forceinline__ void ffma2(uint64_t& d, uint64_t a, uint64_t b) {
    asm("fma.rn.f32x2 %0, %1, %2, %0;" : "+l"(d) : "l"(a), "l"(b));
}
__device__ __forceinline__ uint64_t pack2(float lo, float hi) {
    uint64_t r; asm("mov.b64 %0, {%1, %2};" : "=l"(r) : "f"(lo), "f"(hi)); return r;
}
__device__ __forceinline__ float2 unpack2(uint64_t v) {
    float2 f; asm("mov.b64 {%0, %1}, %2;" : "=f"(f.x), "=f"(f.y) : "l"(v)); return f;
}

// ================= dense: Y[n,108] = act(X[n,FIN] @ W + b) =================
// 512 threads = 4 groups x 128 lanes. Output padded to 128 cols (zero W).
// W staged in shared, k-pair interleaved [k/2][128][2] so one LDS.64 feeds one FFMA2.
// Accumulators are f32x2 (even-k / odd-k partial sums), combined at the end.
template<bool RELU, int FIN>
__global__ __launch_bounds__(512) void gemm_v3(
        const float* __restrict__ X, const float* __restrict__ W,
        const float* __restrict__ b, float* __restrict__ Y, int n) {
    extern __shared__ float sh[];
    float* Ws = sh;                  // FIN*128  (pair-interleaved)
    float* bs = Ws + FIN * 128;      // 128
    float* xs = bs + 128;            // 4*RPB*FIN
    const int tid = threadIdx.x;
    const int t = tid & 127, g = tid >> 7;

    for (int i = tid; i < FIN * 128; i += 512) {
        int k = i >> 7, c = i & 127;
        // dest: pair-interleaved [k>>1][c][k&1]
        Ws[(k >> 1) * 256 + c * 2 + (k & 1)] = (c < HH) ? W[k * HH + c] : 0.f;
    }
    if (tid < 128) bs[tid] = (tid < HH) ? b[tid] : 0.f;

    const int row0 = blockIdx.x * (4 * RPB) + g * RPB;
    float* xsg = xs + g * (RPB * FIN);
    const float4* Xb = (const float4*)(X + (size_t)row0 * FIN);
    const int NV = RPB * FIN / 4;
    for (int i = t; i < NV; i += 128) {
        int r = i / (FIN / 4);
        float4 v = (row0 + r < n) ? Xb[i] : make_float4(0.f, 0.f, 0.f, 0.f);
        ((float4*)xsg)[i] = v;
    }
    __syncthreads();

    uint64_t acc2[RPB];
    {
        uint64_t binit = pack2(bs[t], 0.f);
        #pragma unroll
        for (int r = 0; r < RPB; r++) acc2[r] = binit;
    }
    for (int k = 0; k < FIN; k += 4) {
        uint64_t w01 = *(const uint64_t*)&Ws[((k >> 1)    ) * 256 + 2 * t];
        uint64_t w23 = *(const uint64_t*)&Ws[((k >> 1) + 1) * 256 + 2 * t];
        #pragma unroll
        for (int r = 0; r < RPB; r++) {
            ulonglong2 x = *(const ulonglong2*)&xsg[r * FIN + k];
            ffma2(acc2[r], x.x, w01);
            ffma2(acc2[r], x.y, w23);
        }
    }

    if (t < HH) {
        #pragma unroll
        for (int r = 0; r < RPB; r++) {
            int row = row0 + r;
            if (row < n) {
                float2 p = unpack2(acc2[r]);
                float v = p.x + p.y;
                if (RELU) v = fmaxf(v, 0.f);
                Y[(size_t)row * HH + t] = v;
            }
        }
    }
}

// ================= fused node apply =================
// c = agg/max(deg,1); bundle = [h,c]@Wn + bn; L2-normalize; out = h + relu(.)
__global__ __launch_bounds__(512) void node_apply_v3(
        const float* __restrict__ Hin, const float* __restrict__ agg,
        const int* __restrict__ degi, const float* __restrict__ W,
        const float* __restrict__ b, float* __restrict__ Hout) {
    const int FIN = 216;
    extern __shared__ float sh[];
    float* Ws  = sh;                    // 216*128  (pair-interleaved)
    float* bs  = Ws + FIN * 128;        // 128
    float* xs  = bs + 128;              // 4*NAR*216
    float* red = xs + 4 * NAR * FIN;    // 4 * 5*NAR

    const int tid = threadIdx.x;
    const int t = tid & 127, g = tid >> 7;
    const int warp = t >> 5, lane = t & 31;

    for (int i = tid; i < FIN * 128; i += 512) {
        int k = i >> 7, c = i & 127;
        Ws[(k >> 1) * 256 + c * 2 + (k & 1)] = (c < HH) ? W[k * HH + c] : 0.f;
    }
    if (tid < 128) bs[tid] = (tid < HH) ? b[tid] : 0.f;

    const int row0 = blockIdx.x * (4 * NAR) + g * NAR;
    float* xsg = xs + g * (NAR * FIN);
    const float4* H4 = (const float4*)Hin;
    const float4* A4 = (const float4*)agg;
    for (int i = t; i < NAR * CH4; i += 128) {
        int r = i / CH4, c = i - r * CH4;
        int row = row0 + r;
        float4 h = make_float4(0.f,0.f,0.f,0.f), a = h;
        if (row < NN) {
            h = H4[(size_t)row * CH4 + c];
            a = A4[(size_t)row * CH4 + c];
            float inv = 1.f / fmaxf((float)degi[row], 1.f);
            a.x *= inv; a.y *= inv; a.z *= inv; a.w *= inv;
        }
        *(float4*)&xsg[r*FIN + c*4]       = h;
        *(float4*)&xsg[r*FIN + HH + c*4]  = a;
    }
    __syncthreads();

    uint64_t acc2[NAR];
    {
        uint64_t binit = pack2(bs[t], 0.f);
        #pragma unroll
        for (int r = 0; r < NAR; r++) acc2[r] = binit;
    }
    for (int k = 0; k < FIN; k += 4) {
        uint64_t w01 = *(const uint64_t*)&Ws[((k >> 1)    ) * 256 + 2 * t];
        uint64_t w23 = *(const uint64_t*)&Ws[((k >> 1) + 1) * 256 + 2 * t];
        #pragma unroll
        for (int r = 0; r < NAR; r++) {
            ulonglong2 x = *(const ulonglong2*)&xsg[r * FIN + k];
            ffma2(acc2[r], x.x, w01);
            ffma2(acc2[r], x.y, w23);
        }
    }

    float acc[NAR];
    #pragma unroll
    for (int r = 0; r < NAR; r++) {
        float2 p = unpack2(acc2[r]);
        acc[r] = p.x + p.y;          // padded lanes produce exact zeros
    }

    // row L2 norms
    float* redg = red + g * (5 * NAR);
    #pragma unroll
    for (int r = 0; r < NAR; r++) {
        float v = acc[r] * acc[r];
        #pragma unroll
        for (int off = 16; off > 0; off >>= 1)
            v += __shfl_down_sync(0xffffffffu, v, off);
        if (lane == 0) redg[warp * NAR + r] = v;
    }
    __syncthreads();
    if (t < NAR) {
        float s = redg[t] + redg[NAR+t] + redg[2*NAR+t] + redg[3*NAR+t];
        redg[4*NAR + t] = fmaxf(sqrtf(s), 1e-12f);
    }
    __syncthreads();

    if (t < HH) {
        #pragma unroll
        for (int r = 0; r < NAR; r++) {
            int row = row0 + r;
            if (row < NN) {
                float inv = 1.f / redg[4*NAR + r];
                Hout[(size_t)row * HH + t] = xsg[r*FIN + t] + fmaxf(acc[r] * inv, 0.f);
            }
        }
    }
}

// ================= CSR build =================
__global__ void deg_cnt_kernel(const int* __restrict__ dst, const int* __restrict__ gid,
                               int* __restrict__ degi, float* __restrict__ cnt) {
    int tk = blockIdx.x * blockDim.x + threadIdx.x;
    if (tk < EE) atomicAdd(&degi[dst[tk]], 1);
    if (tk < NN) atomicAdd(&cnt[gid[tk]], 1.f);
}

__global__ void scan1(const int* __restrict__ degi, int* __restrict__ off,
                      int* __restrict__ bsum) {   // 512 thr, 512 elems/block
    __shared__ int shi[512];
    int i = blockIdx.x * 512 + threadIdx.x;
    int x = (i < NN) ? degi[i] : 0;
    shi[threadIdx.x] = x;
    __syncthreads();
    for (int d = 1; d < 512; d <<= 1) {
        int v = (threadIdx.x >= d) ? shi[threadIdx.x - d] : 0;
        __syncthreads();
        shi[threadIdx.x] += v;
        __syncthreads();
    }
    if (i < NN) off[i] = shi[threadIdx.x] - x;       // exclusive within block
    if (threadIdx.x == 511) bsum[blockIdx.x] = shi[511];
}

__global__ void scan2(int* __restrict__ bsum, int nb) {  // 1 block, 128 thr
    __shared__ int shi[128];
    int x = (threadIdx.x < nb) ? bsum[threadIdx.x] : 0;
    shi[threadIdx.x] = x;
    __syncthreads();
    for (int d = 1; d < 128; d <<= 1) {
        int v = (threadIdx.x >= d) ? shi[threadIdx.x - d] : 0;
        __syncthreads();
        shi[threadIdx.x] += v;
        __syncthreads();
    }
    if (threadIdx.x < nb) bsum[threadIdx.x] = shi[threadIdx.x] - x;  // exclusive
}

__global__ void scan3(int* __restrict__ off, const int* __restrict__ bsum) {
    int i = blockIdx.x * blockDim.x + threadIdx.x;
    if (i < NN) off[i] += bsum[i >> 9];
}

__global__ void csr_fill(const int* __restrict__ src, const int* __restrict__ dst,
                         int* __restrict__ cur, int* __restrict__ csr) {
    int e = blockIdx.x * blockDim.x + threadIdx.x;
    if (e < EE) {
        int d = dst[e];
        int p = atomicAdd(&cur[d], 1);
        csr[p] = src[e];
    }
}

// ================= gather aggregation: one warp per node, unroll x2 =================
__global__ void gather_agg(const float* __restrict__ m, const int* __restrict__ off,
                           const int* __restrict__ csr, float* __restrict__ agg) {
    int w = (blockIdx.x * blockDim.x + threadIdx.x) >> 5;
    int lane = threadIdx.x & 31;
    if (w >= NN) return;
    int s0 = off[w];
    int s1 = (w + 1 < NN) ? off[w + 1] : EE;
    float4 acc0 = make_float4(0.f, 0.f, 0.f, 0.f);
    float4 acc1 = make_float4(0.f, 0.f, 0.f, 0.f);
    const float4* m4 = (const float4*)m;
    int j = s0;
    if (lane < CH4) {
        for (; j + 1 < s1; j += 2) {
            int sa = csr[j], sb = csr[j + 1];
            float4 va = m4[(size_t)sa * CH4 + lane];
            float4 vb = m4[(size_t)sb * CH4 + lane];
            acc0.x += va.x; acc0.y += va.y; acc0.z += va.z; acc0.w += va.w;
            acc1.x += vb.x; acc1.y += vb.y; acc1.z += vb.z; acc1.w += vb.w;
        }
        if (j < s1) {
            int sa = csr[j];
            float4 va = m4[(size_t)sa * CH4 + lane];
            acc0.x += va.x; acc0.y += va.y; acc0.z += va.z; acc0.w += va.w;
        }
        acc0.x += acc1.x; acc0.y += acc1.y; acc0.z += acc1.z; acc0.w += acc1.w;
        ((float4*)agg)[(size_t)w * CH4 + lane] = acc0;
    }
}

// ================= readout =================
__device__ __forceinline__ void red_add_v4(float* a, float4 v) {
    asm volatile("red.global.add.v4.f32 [%0], {%1, %2, %3, %4};"
                 :: "l"(a), "f"(v.x), "f"(v.y), "f"(v.z), "f"(v.w)
                 : "memory");
}

__global__ void graph_pool(const float* __restrict__ Hfin, const int* __restrict__ gid,
                           float* __restrict__ s) {
    int tk = blockIdx.x * blockDim.x + threadIdx.x;
    if (tk >= NN * CH4) return;
    int nidx = tk / CH4;
    int c    = tk - nidx * CH4;
    int g    = gid[nidx];
    float4 v = *reinterpret_cast<const float4*>(Hfin + (size_t)nidx * HH + c * 4);
    red_add_v4(s + (size_t)g * HH + c * 4, v);
}

__global__ void finalize(const float* __restrict__ s, const float* __restrict__ cnt,
                         float* __restrict__ out) {
    int tk = blockIdx.x * blockDim.x + threadIdx.x;
    if (tk < GG * HH) {
        int g = tk / HH;
        out[tk] = s[tk] / fmaxf(cnt[g], 1.f);
    }
}

// ================= launch =================
extern "C" void kernel_launch(void* const* d_in, const int* in_sizes, int n_in,
                              void* d_out, int out_size) {
    const float* nodes_feat = (const float*)d_in[0];
    const int*   src  = (const int*)d_in[4];
    const int*   dst  = (const int*)d_in[5];
    const int*   gid  = (const int*)d_in[6];
    const float* W_emb = (const float*)d_in[7];
    const float* b_emb = (const float*)d_in[8];
    const float* Wp1   = (const float*)d_in[9];
    const float* bp1   = (const float*)d_in[10];
    const float* Wn1   = (const float*)d_in[11];
    const float* bn1   = (const float*)d_in[12];
    const float* Wp2   = (const float*)d_in[13];
    const float* bp2   = (const float*)d_in[14];
    const float* Wn2   = (const float*)d_in[15];
    const float* bn2   = (const float*)d_in[16];
    float* out = (float*)d_out;

    float *p_h0, *p_m, *p_agg, *p_h1, *p_s, *p_cnt;
    int *p_degi, *p_off, *p_cur, *p_csr, *p_bsum;
    cudaGetSymbolAddress((void**)&p_h0,   g_h0);
    cudaGetSymbolAddress((void**)&p_m,    g_m);
    cudaGetSymbolAddress((void**)&p_agg,  g_agg);
    cudaGetSymbolAddress((void**)&p_h1,   g_h1);
    cudaGetSymbolAddress((void**)&p_s,    g_s);
    cudaGetSymbolAddress((void**)&p_cnt,  g_cnt);
    cudaGetSymbolAddress((void**)&p_degi, g_degi);
    cudaGetSymbolAddress((void**)&p_off,  g_off);
    cudaGetSymbolAddress((void**)&p_cur,  g_cur);
    cudaGetSymbolAddress((void**)&p_csr,  g_csr);
    cudaGetSymbolAddress((void**)&p_bsum, g_bsum);

    const int smem_emb  = (FIN_EMB*128 + 128 + 4*RPB*FIN_EMB) * 4;   // ~49.7 KB
    const int smem_pool = (HH*128 + 128 + 4*RPB*HH) * 4;             // ~83.5 KB
    const int smem_na   = (216*128 + 128 + 4*NAR*216 + 4*5*NAR) * 4; // ~167.7 KB
    cudaFuncSetAttribute(gemm_v3<false, FIN_EMB>, cudaFuncAttributeMaxDynamicSharedMemorySize, smem_emb);
    cudaFuncSetAttribute(gemm_v3<true,  HH>,      cudaFuncAttributeMaxDynamicSharedMemorySize, smem_pool);
    cudaFuncSetAttribute(node_apply_v3,           cudaFuncAttributeMaxDynamicSharedMemorySize, smem_na);

    cudaMemsetAsync(p_degi, 0, (size_t)NN * sizeof(int));
    cudaMemsetAsync(p_s,    0, (size_t)GG * HH * sizeof(float));
    cudaMemsetAsync(p_cnt,  0, (size_t)GG * sizeof(float));

    const int gemm_blocks = (NN + 4*RPB - 1) / (4*RPB);   // 782
    const int na_blocks   = (NN + 4*NAR - 1) / (4*NAR);   // 782
    const int nb_scan     = (NN + 511) / 512;             // 98
    const int gath_blocks = (NN * 32 + 255) / 256;        // 6250

    // h0 = X @ W_emb + b_emb
    gemm_v3<false, FIN_EMB><<<gemm_blocks, 512, smem_emb>>>(nodes_feat, W_emb, b_emb, p_h0, NN);

    // degrees + graph counts, then CSR by dst (shared by both layers)
    deg_cnt_kernel<<<(EE + 255) / 256, 256>>>(dst, gid, p_degi, p_cnt);
    scan1<<<nb_scan, 512>>>(p_degi, p_off, p_bsum);
    scan2<<<1, 128>>>(p_bsum, nb_scan);
    scan3<<<(NN + 255) / 256, 256>>>(p_off, p_bsum);
    cudaMemcpyAsync(p_cur, p_off, (size_t)NN * sizeof(int), cudaMemcpyDeviceToDevice);
    csr_fill<<<(EE + 255) / 256, 256>>>(src, dst, p_cur, p_csr);

    // ---- layer 1 ----
    gemm_v3<true, HH><<<gemm_blocks, 512, smem_pool>>>(p_h0, Wp1, bp1, p_m, NN);
    gather_agg<<<gath_blocks, 256>>>(p_m, p_off, p_csr, p_agg);
    node_apply_v3<<<na_blocks, 512, smem_na>>>(p_h0, p_agg, p_degi, Wn1, bn1, p_h1);

    // ---- layer 2 ----
    gemm_v3<true, HH><<<gemm_blocks, 512, smem_pool>>>(p_h1, Wp2, bp2, p_m, NN);
    gather_agg<<<gath_blocks, 256>>>(p_m, p_off, p_csr, p_agg);
    node_apply_v3<<<na_blocks, 512, smem_na>>>(p_h1, p_agg, p_degi, Wn2, bn2, p_h0);

    // ---- readout ----
    graph_pool<<<(NN * CH4 + 255) / 256, 256>>>(p_h0, gid, p_s);
    finalize<<<(GG * HH + 127) / 128, 128>>>(p_s, p_cnt, out);
}

// round 4
// speedup vs baseline: 1.9174x; 1.0050x over previous
#include <cuda_runtime.h>
#include <cuda_bf16.h>
#include <math.h>
#include <stdint.h>

// Problem constants (fixed by the reference)
#define NN  50000
#define EE  800000
#define GG  128
#define HH  108
#define CH4 (HH/4)
#define XS  40            // X smem row stride (bf16 elems) — conflict-free banks

// ---------------- scratch (no allocations allowed) ----------------
__device__ __align__(16) float g_h0 [NN*HH];
__device__ __align__(16) float g_m  [NN*HH];
__device__ __align__(16) float g_agg[NN*HH];
__device__ __align__(16) float g_h1 [NN*HH];
__device__ __align__(16) float g_s  [GG*HH];
__device__ int   g_degi[NN];
__device__ int   g_off [NN];
__device__ int   g_cur [NN];
__device__ int   g_csr [EE];
__device__ int   g_bsum[128];
__device__ float g_cnt[GG];

// ---------------- mma.sync m16n8k16 bf16 -> f32 ----------------
__device__ __forceinline__ void mma16816(float* c,
        uint32_t a0, uint32_t a1, uint32_t a2, uint32_t a3,
        uint32_t b0, uint32_t b1) {
    asm volatile(
        "mma.sync.aligned.m16n8k16.row.col.f32.bf16.bf16.f32 "
        "{%0,%1,%2,%3}, {%4,%5,%6,%7}, {%8,%9}, {%0,%1,%2,%3};"
        : "+f"(c[0]), "+f"(c[1]), "+f"(c[2]), "+f"(c[3])
        : "r"(a0), "r"(a1), "r"(a2), "r"(a3), "r"(b0), "r"(b1));
}

__device__ __forceinline__ void split_bf16(float v, __nv_bfloat16& h, __nv_bfloat16& l) {
    h = __float2bfloat16(v);
    l = __float2bfloat16(v - __bfloat162float(h));
}

// stage W[K][108] -> smem transposed/split: Wh/Wl [n (128)][k (WS stride)]
template<int K, int WS>
__device__ __forceinline__ void stage_W(const float* __restrict__ W,
        __nv_bfloat16* Wh, __nv_bfloat16* Wl, int tid) {
    // zero both arrays (contiguous): 2*128*WS bf16 = 128*WS u32
    uint32_t* z = (uint32_t*)Wh;
    for (int i = tid; i < 128 * WS; i += 256) z[i] = 0u;
    __syncthreads();
    for (int i = tid; i < K * HH; i += 256) {
        int k = i / HH, nn = i - k * HH;
        __nv_bfloat16 h, l;
        split_bf16(W[i], h, l);
        Wh[nn * WS + k] = h;
        Wl[nn * WS + k] = l;
    }
}

// ================= GEMM: Y[n,108] = act(X[n,K] @ W + b) =================
// block: 128 rows x 128 cols (108 valid), 256 thr = 8 warps (4 M x 2 N)
template<int K, int KPAD, bool RELU>
__global__ __launch_bounds__(256) void mma_gemm(
        const float* __restrict__ X, const float* __restrict__ W,
        const float* __restrict__ b, float* __restrict__ Y, int n) {
    const int WS = KPAD + 8;
    extern __shared__ char sh[];
    __nv_bfloat16* Wh = (__nv_bfloat16*)sh;
    __nv_bfloat16* Wl = Wh + 128 * WS;
    __nv_bfloat16* Xh = Wl + 128 * WS;
    __nv_bfloat16* Xl = Xh + 128 * XS;
    float* bs = (float*)(Xl + 128 * XS);

    const int tid = threadIdx.x;
    const int l = tid & 31, wid = tid >> 5;
    const int wm = wid & 3, wn = wid >> 2;
    const int row0 = blockIdx.x * 128;

    stage_W<K, WS>(W, Wh, Wl, tid);
    if (tid < 128) bs[tid] = (tid < HH) ? b[tid] : 0.f;

    float acc[2][8][4];
    #pragma unroll
    for (int mt = 0; mt < 2; mt++)
        #pragma unroll
        for (int nt = 0; nt < 8; nt++)
            #pragma unroll
            for (int i = 0; i < 4; i++) acc[mt][nt][i] = 0.f;

    for (int c0 = 0; c0 < KPAD; c0 += 32) {
        __syncthreads();
        for (int i = tid; i < 128 * 32; i += 256) {
            int r = i >> 5, kk = i & 31;
            int row = row0 + r, k = c0 + kk;
            float v = (row < n && k < K) ? X[(size_t)row * K + k] : 0.f;
            __nv_bfloat16 h, lo;
            split_bf16(v, h, lo);
            Xh[r * XS + kk] = h;
            Xl[r * XS + kk] = lo;
        }
        __syncthreads();

        #pragma unroll
        for (int ks = 0; ks < 2; ks++) {
            const int kb = ks * 16;
            uint32_t ah[2][4], al[2][4];
            #pragma unroll
            for (int mt = 0; mt < 2; mt++) {
                int r  = wm * 32 + mt * 16 + (l >> 2);
                int kk = kb + ((l & 3) << 1);
                ah[mt][0] = *(const uint32_t*)&Xh[r * XS + kk];
                ah[mt][1] = *(const uint32_t*)&Xh[(r + 8) * XS + kk];
                ah[mt][2] = *(const uint32_t*)&Xh[r * XS + kk + 8];
                ah[mt][3] = *(const uint32_t*)&Xh[(r + 8) * XS + kk + 8];
                al[mt][0] = *(const uint32_t*)&Xl[r * XS + kk];
                al[mt][1] = *(const uint32_t*)&Xl[(r + 8) * XS + kk];
                al[mt][2] = *(const uint32_t*)&Xl[r * XS + kk + 8];
                al[mt][3] = *(const uint32_t*)&Xl[(r + 8) * XS + kk + 8];
            }
            #pragma unroll
            for (int nt = 0; nt < 8; nt++) {
                int nn2 = wn * 64 + nt * 8 + (l >> 2);
                int kg  = c0 + kb + ((l & 3) << 1);
                uint32_t bh0 = *(const uint32_t*)&Wh[nn2 * WS + kg];
                uint32_t bh1 = *(const uint32_t*)&Wh[nn2 * WS + kg + 8];
                uint32_t bl0 = *(const uint32_t*)&Wl[nn2 * WS + kg];
                uint32_t bl1 = *(const uint32_t*)&Wl[nn2 * WS + kg + 8];
                #pragma unroll
                for (int mt = 0; mt < 2; mt++) {
                    mma16816(acc[mt][nt], ah[mt][0], ah[mt][1], ah[mt][2], ah[mt][3], bh0, bh1);
                    mma16816(acc[mt][nt], ah[mt][0], ah[mt][1], ah[mt][2], ah[mt][3], bl0, bl1);
                    mma16816(acc[mt][nt], al[mt][0], al[mt][1], al[mt][2], al[mt][3], bh0, bh1);
                }
            }
        }
    }

    // epilogue: bias (+relu), direct store
    #pragma unroll
    for (int mt = 0; mt < 2; mt++) {
        #pragma unroll
        for (int nt = 0; nt < 8; nt++) {
            int col = wn * 64 + nt * 8 + ((l & 3) << 1);
            if (col + 1 < HH) {
                int row = row0 + wm * 32 + mt * 16 + (l >> 2);
                float v0 = acc[mt][nt][0] + bs[col];
                float v1 = acc[mt][nt][1] + bs[col + 1];
                float v2 = acc[mt][nt][2] + bs[col];
                float v3 = acc[mt][nt][3] + bs[col + 1];
                if (RELU) { v0 = fmaxf(v0, 0.f); v1 = fmaxf(v1, 0.f);
                            v2 = fmaxf(v2, 0.f); v3 = fmaxf(v3, 0.f); }
                if (row < n)     *(float2*)&Y[(size_t)row * HH + col]       = make_float2(v0, v1);
                if (row + 8 < n) *(float2*)&Y[(size_t)(row + 8) * HH + col] = make_float2(v2, v3);
            }
        }
    }
}

// ================= fused node apply (tensor-core) =================
// X = [Hin, agg/max(deg,1)] (K=216, KPAD=224); bundle = X@Wn + bn;
// L2-normalize row; out = Hin + relu(bundle/norm)
__global__ __launch_bounds__(256) void mma_napply(
        const float* __restrict__ Hin, const float* __restrict__ agg,
        const int* __restrict__ degi, const float* __restrict__ W,
        const float* __restrict__ b, float* __restrict__ Hout) {
    const int K = 216, KPAD = 224, WS = KPAD + 8, ES = 136;
    extern __shared__ char sh[];
    __nv_bfloat16* Wh = (__nv_bfloat16*)sh;
    __nv_bfloat16* Wl = Wh + 128 * WS;
    __nv_bfloat16* Xh = Wl + 128 * WS;
    __nv_bfloat16* Xl = Xh + 128 * XS;
    float* bs  = (float*)(Xl + 128 * XS);
    float* idg = bs + 128;
    float* epi = (float*)sh;               // aliases W region after mainloop

    const int tid = threadIdx.x;
    const int l = tid & 31, wid = tid >> 5;
    const int wm = wid & 3, wn = wid >> 2;
    const int row0 = blockIdx.x * 128;

    stage_W<K, WS>(W, Wh, Wl, tid);
    if (tid < 128) {
        bs[tid] = (tid < HH) ? b[tid] : 0.f;
        int row = row0 + tid;
        idg[tid] = (row < NN) ? 1.f / fmaxf((float)degi[row], 1.f) : 0.f;
    }

    float acc[2][8][4];
    #pragma unroll
    for (int mt = 0; mt < 2; mt++)
        #pragma unroll
        for (int nt = 0; nt < 8; nt++)
            #pragma unroll
            for (int i = 0; i < 4; i++) acc[mt][nt][i] = 0.f;

    for (int c0 = 0; c0 < KPAD; c0 += 32) {
        __syncthreads();
        for (int i = tid; i < 128 * 32; i += 256) {
            int r = i >> 5, kk = i & 31;
            int row = row0 + r, k = c0 + kk;
            float v = 0.f;
            if (row < NN) {
                if (k < HH)      v = Hin[(size_t)row * HH + k];
                else if (k < K)  v = agg[(size_t)row * HH + (k - HH)] * idg[r];
            }
            __nv_bfloat16 h, lo;
            split_bf16(v, h, lo);
            Xh[r * XS + kk] = h;
            Xl[r * XS + kk] = lo;
        }
        __syncthreads();

        #pragma unroll
        for (int ks = 0; ks < 2; ks++) {
            const int kb = ks * 16;
            uint32_t ah[2][4], al[2][4];
            #pragma unroll
            for (int mt = 0; mt < 2; mt++) {
                int r  = wm * 32 + mt * 16 + (l >> 2);
                int kk = kb + ((l & 3) << 1);
                ah[mt][0] = *(const uint32_t*)&Xh[r * XS + kk];
                ah[mt][1] = *(const uint32_t*)&Xh[(r + 8) * XS + kk];
                ah[mt][2] = *(const uint32_t*)&Xh[r * XS + kk + 8];
                ah[mt][3] = *(const uint32_t*)&Xh[(r + 8) * XS + kk + 8];
                al[mt][0] = *(const uint32_t*)&Xl[r * XS + kk];
                al[mt][1] = *(const uint32_t*)&Xl[(r + 8) * XS + kk];
                al[mt][2] = *(const uint32_t*)&Xl[r * XS + kk + 8];
                al[mt][3] = *(const uint32_t*)&Xl[(r + 8) * XS + kk + 8];
            }
            #pragma unroll
            for (int nt = 0; nt < 8; nt++) {
                int nn2 = wn * 64 + nt * 8 + (l >> 2);
                int kg  = c0 + kb + ((l & 3) << 1);
                uint32_t bh0 = *(const uint32_t*)&Wh[nn2 * WS + kg];
                uint32_t bh1 = *(const uint32_t*)&Wh[nn2 * WS + kg + 8];
                uint32_t bl0 = *(const uint32_t*)&Wl[nn2 * WS + kg];
                uint32_t bl1 = *(const uint32_t*)&Wl[nn2 * WS + kg + 8];
                #pragma unroll
                for (int mt = 0; mt < 2; mt++) {
                    mma16816(acc[mt][nt], ah[mt][0], ah[mt][1], ah[mt][2], ah[mt][3], bh0, bh1);
                    mma16816(acc[mt][nt], ah[mt][0], ah[mt][1], ah[mt][2], ah[mt][3], bl0, bl1);
                    mma16816(acc[mt][nt], al[mt][0], al[mt][1], al[mt][2], al[mt][3], bh0, bh1);
                }
            }
        }
    }

    // dump acc (+bias) to smem (aliasing W) for row-norm reduction
    __syncthreads();
    #pragma unroll
    for (int mt = 0; mt < 2; mt++) {
        #pragma unroll
        for (int nt = 0; nt < 8; nt++) {
            int r   = wm * 32 + mt * 16 + (l >> 2);
            int col = wn * 64 + nt * 8 + ((l & 3) << 1);
            *(float2*)&epi[r * ES + col] =
                make_float2(acc[mt][nt][0] + bs[col], acc[mt][nt][1] + bs[col + 1 < 128 ? col + 1 : col]);
            *(float2*)&epi[(r + 8) * ES + col] =
                make_float2(acc[mt][nt][2] + bs[col], acc[mt][nt][3] + bs[col + 1 < 128 ? col + 1 : col]);
        }
    }
    __syncthreads();

    // norm + residual + relu: each warp owns 16 rows
    for (int rr = 0; rr < 16; rr++) {
        int r = wid * 16 + rr;
        int row = row0 + r;
        if (row >= NN) continue;
        float v[4]; float s = 0.f;
        #pragma unroll
        for (int j = 0; j < 4; j++) {
            int c = l + 32 * j;
            v[j] = (c < HH) ? epi[r * ES + c] : 0.f;
            s += v[j] * v[j];
        }
        #pragma unroll
        for (int off = 16; off > 0; off >>= 1)
            s += __shfl_xor_sync(0xffffffffu, s, off);
        float inv = 1.f / fmaxf(sqrtf(s), 1e-12f);
        #pragma unroll
        for (int j = 0; j < 4; j++) {
            int c = l + 32 * j;
            if (c < HH)
                Hout[(size_t)row * HH + c] = Hin[(size_t)row * HH + c] + fmaxf(v[j] * inv, 0.f);
        }
    }
}

// ================= CSR build =================
__global__ void deg_cnt_kernel(const int* __restrict__ dst, const int* __restrict__ gid,
                               int* __restrict__ degi, float* __restrict__ cnt) {
    int tk = blockIdx.x * blockDim.x + threadIdx.x;
    if (tk < EE) atomicAdd(&degi[dst[tk]], 1);
    if (tk < NN) atomicAdd(&cnt[gid[tk]], 1.f);
}

__global__ void scan1(const int* __restrict__ degi, int* __restrict__ off,
                      int* __restrict__ bsum) {
    __shared__ int shi[512];
    int i = blockIdx.x * 512 + threadIdx.x;
    int x = (i < NN) ? degi[i] : 0;
    shi[threadIdx.x] = x;
    __syncthreads();
    for (int d = 1; d < 512; d <<= 1) {
        int v = (threadIdx.x >= d) ? shi[threadIdx.x - d] : 0;
        __syncthreads();
        shi[threadIdx.x] += v;
        __syncthreads();
    }
    if (i < NN) off[i] = shi[threadIdx.x] - x;
    if (threadIdx.x == 511) bsum[blockIdx.x] = shi[511];
}

__global__ void scan2(int* __restrict__ bsum, int nb) {
    __shared__ int shi[128];
    int x = (threadIdx.x < nb) ? bsum[threadIdx.x] : 0;
    shi[threadIdx.x] = x;
    __syncthreads();
    for (int d = 1; d < 128; d <<= 1) {
        int v = (threadIdx.x >= d) ? shi[threadIdx.x - d] : 0;
        __syncthreads();
        shi[threadIdx.x] += v;
        __syncthreads();
    }
    if (threadIdx.x < nb) bsum[threadIdx.x] = shi[threadIdx.x] - x;
}

__global__ void scan3(int* __restrict__ off, const int* __restrict__ bsum) {
    int i = blockIdx.x * blockDim.x + threadIdx.x;
    if (i < NN) off[i] += bsum[i >> 9];
}

__global__ void csr_fill(const int* __restrict__ src, const int* __restrict__ dst,
                         int* __restrict__ cur, int* __restrict__ csr) {
    int e = blockIdx.x * blockDim.x + threadIdx.x;
    if (e < EE) {
        int d = dst[e];
        int p = atomicAdd(&cur[d], 1);
        csr[p] = src[e];
    }
}

// ================= gather aggregation: one warp per node =================
__global__ void gather_agg(const float* __restrict__ m, const int* __restrict__ off,
                           const int* __restrict__ csr, float* __restrict__ agg) {
    int w = (blockIdx.x * blockDim.x + threadIdx.x) >> 5;
    int lane = threadIdx.x & 31;
    if (w >= NN) return;
    int s0 = off[w];
    int s1 = (w + 1 < NN) ? off[w + 1] : EE;
    float4 acc0 = make_float4(0.f, 0.f, 0.f, 0.f);
    float4 acc1 = make_float4(0.f, 0.f, 0.f, 0.f);
    const float4* m4 = (const float4*)m;
    int j = s0;
    if (lane < CH4) {
        for (; j + 1 < s1; j += 2) {
            int sa = csr[j], sb = csr[j + 1];
            float4 va = m4[(size_t)sa * CH4 + lane];
            float4 vb = m4[(size_t)sb * CH4 + lane];
            acc0.x += va.x; acc0.y += va.y; acc0.z += va.z; acc0.w += va.w;
            acc1.x += vb.x; acc1.y += vb.y; acc1.z += vb.z; acc1.w += vb.w;
        }
        if (j < s1) {
            int sa = csr[j];
            float4 va = m4[(size_t)sa * CH4 + lane];
            acc0.x += va.x; acc0.y += va.y; acc0.z += va.z; acc0.w += va.w;
        }
        acc0.x += acc1.x; acc0.y += acc1.y; acc0.z += acc1.z; acc0.w += acc1.w;
        ((float4*)agg)[(size_t)w * CH4 + lane] = acc0;
    }
}

// ================= readout =================
__device__ __forceinline__ void red_add_v4(float* a, float4 v) {
    asm volatile("red.global.add.v4.f32 [%0], {%1, %2, %3, %4};"
                 :: "l"(a), "f"(v.x), "f"(v.y), "f"(v.z), "f"(v.w)
                 : "memory");
}

__global__ void graph_pool(const float* __restrict__ Hfin, const int* __restrict__ gid,
                           float* __restrict__ s) {
    int tk = blockIdx.x * blockDim.x + threadIdx.x;
    if (tk >= NN * CH4) return;
    int nidx = tk / CH4;
    int c    = tk - nidx * CH4;
    int g    = gid[nidx];
    float4 v = *reinterpret_cast<const float4*>(Hfin + (size_t)nidx * HH + c * 4);
    red_add_v4(s + (size_t)g * HH + c * 4, v);
}

__global__ void finalize(const float* __restrict__ s, const float* __restrict__ cnt,
                         float* __restrict__ out) {
    int tk = blockIdx.x * blockDim.x + threadIdx.x;
    if (tk < GG * HH) {
        int g = tk / HH;
        out[tk] = s[tk] / fmaxf(cnt[g], 1.f);
    }
}

// ================= launch =================
extern "C" void kernel_launch(void* const* d_in, const int* in_sizes, int n_in,
                              void* d_out, int out_size) {
    const float* nodes_feat = (const float*)d_in[0];
    const int*   src  = (const int*)d_in[4];
    const int*   dst  = (const int*)d_in[5];
    const int*   gid  = (const int*)d_in[6];
    const float* W_emb = (const float*)d_in[7];
    const float* b_emb = (const float*)d_in[8];
    const float* Wp1   = (const float*)d_in[9];
    const float* bp1   = (const float*)d_in[10];
    const float* Wn1   = (const float*)d_in[11];
    const float* bn1   = (const float*)d_in[12];
    const float* Wp2   = (const float*)d_in[13];
    const float* bp2   = (const float*)d_in[14];
    const float* Wn2   = (const float*)d_in[15];
    const float* bn2   = (const float*)d_in[16];
    float* out = (float*)d_out;

    float *p_h0, *p_m, *p_agg, *p_h1, *p_s, *p_cnt;
    int *p_degi, *p_off, *p_cur, *p_csr, *p_bsum;
    cudaGetSymbolAddress((void**)&p_h0,   g_h0);
    cudaGetSymbolAddress((void**)&p_m,    g_m);
    cudaGetSymbolAddress((void**)&p_agg,  g_agg);
    cudaGetSymbolAddress((void**)&p_h1,   g_h1);
    cudaGetSymbolAddress((void**)&p_s,    g_s);
    cudaGetSymbolAddress((void**)&p_cnt,  g_cnt);
    cudaGetSymbolAddress((void**)&p_degi, g_degi);
    cudaGetSymbolAddress((void**)&p_off,  g_off);
    cudaGetSymbolAddress((void**)&p_cur,  g_cur);
    cudaGetSymbolAddress((void**)&p_csr,  g_csr);
    cudaGetSymbolAddress((void**)&p_bsum, g_bsum);

    // smem sizes: W(hi+lo) + X(hi+lo) + bias (+ idg for napply)
    const int smem_emb  = (2*128*(64+8))*2  + (2*128*XS)*2 + 512;         // 57,856
    const int smem_pool = (2*128*(128+8))*2 + (2*128*XS)*2 + 512;         // 90,624
    const int smem_na   = (2*128*(224+8))*2 + (2*128*XS)*2 + 512 + 512;   // 140,288
    cudaFuncSetAttribute(mma_gemm<64, 64, false>,  cudaFuncAttributeMaxDynamicSharedMemorySize, smem_emb);
    cudaFuncSetAttribute(mma_gemm<108, 128, true>, cudaFuncAttributeMaxDynamicSharedMemorySize, smem_pool);
    cudaFuncSetAttribute(mma_napply,               cudaFuncAttributeMaxDynamicSharedMemorySize, smem_na);

    cudaMemsetAsync(p_degi, 0, (size_t)NN * sizeof(int));
    cudaMemsetAsync(p_s,    0, (size_t)GG * HH * sizeof(float));
    cudaMemsetAsync(p_cnt,  0, (size_t)GG * sizeof(float));

    const int mma_blocks  = (NN + 127) / 128;   // 391
    const int nb_scan     = (NN + 511) / 512;   // 98
    const int gath_blocks = (NN * 32 + 255) / 256;

    // h0 = X @ W_emb + b_emb
    mma_gemm<64, 64, false><<<mma_blocks, 256, smem_emb>>>(nodes_feat, W_emb, b_emb, p_h0, NN);

    // degrees + graph counts, then CSR by dst (shared by both layers)
    deg_cnt_kernel<<<(EE + 255) / 256, 256>>>(dst, gid, p_degi, p_cnt);
    scan1<<<nb_scan, 512>>>(p_degi, p_off, p_bsum);
    scan2<<<1, 128>>>(p_bsum, nb_scan);
    scan3<<<(NN + 255) / 256, 256>>>(p_off, p_bsum);
    cudaMemcpyAsync(p_cur, p_off, (size_t)NN * sizeof(int), cudaMemcpyDeviceToDevice);
    csr_fill<<<(EE + 255) / 256, 256>>>(src, dst, p_cur, p_csr);

    // ---- layer 1 ----
    mma_gemm<108, 128, true><<<mma_blocks, 256, smem_pool>>>(p_h0, Wp1, bp1, p_m, NN);
    gather_agg<<<gath_blocks, 256>>>(p_m, p_off, p_csr, p_agg);
    mma_napply<<<mma_blocks, 256, smem_na>>>(p_h0, p_agg, p_degi, Wn1, bn1, p_h1);

    // ---- layer 2 ----
    mma_gemm<108, 128, true><<<mma_blocks, 256, smem_pool>>>(p_h1, Wp2, bp2, p_m, NN);
    gather_agg<<<gath_blocks, 256>>>(p_m, p_off, p_csr, p_agg);
    mma_napply<<<mma_blocks, 256, smem_na>>>(p_h1, p_agg, p_degi, Wn2, bn2, p_h0);

    // ---- readout ----
    graph_pool<<<(NN * CH4 + 255) / 256, 256>>>(p_h0, gid, p_s);
    finalize<<<(GG * HH + 127) / 128, 128>>>(p_s, p_cnt, out);
}